// round 2
// baseline (speedup 1.0000x reference)
#include <cuda_runtime.h>
#include <cuda_fp16.h>
#include <math.h>

#define NN 4096
#define DD 512
#define INV_EPS (1.0f/8.0f)
#define STABZ 1e-8f

// ---- device scratch (no allocations allowed) ----
__device__ float  g_u[NN];
__device__ float  g_v[NN];
__device__ float  g_sn[NN];
__device__ float  g_tn[NN];
__device__ __half g_Kh[(size_t)NN * NN];     // 32 MB fp16 Gibbs kernel for matvecs
__device__ float  g_colpart[32 * NN];
__device__ float  g_losspart[NN];

// ---------------- row squared-norms of S (y=0) and T (y=1) ----------------
__global__ void norm_kernel(const float* __restrict__ S, const float* __restrict__ T) {
    const float* src = blockIdx.y ? T : S;
    float*       dst = blockIdx.y ? g_tn : g_sn;
    int row = blockIdx.x;
    const float4* p = (const float4*)(src + (size_t)row * DD);
    float4 x = p[threadIdx.x];                  // 128 threads * 4 = 512
    float s = x.x * x.x + x.y * x.y + x.z * x.z + x.w * x.w;
    #pragma unroll
    for (int o = 16; o > 0; o >>= 1) s += __shfl_down_sync(0xffffffffu, s, o);
    __shared__ float sh[4];
    if ((threadIdx.x & 31) == 0) sh[threadIdx.x >> 5] = s;
    __syncthreads();
    if (threadIdx.x == 0) dst[row] = sh[0] + sh[1] + sh[2] + sh[3];
}

// ---------------- v = ones ----------------
__global__ void init_v_kernel() {
    int i = blockIdx.x * 256 + threadIdx.x;
    if (i < NN) g_v[i] = 1.0f;
}

// ---------------- fused GEMM: dot = S @ T^T ; C = sqrt(max(sn+tn-2dot,0)); K = exp(-C/8) ----------------
// 128x128 block tile, BK=8, 256 threads, 8x8 per thread.
__global__ __launch_bounds__(256, 2)
void gemm_fused_kernel(const float* __restrict__ S, const float* __restrict__ T,
                       float* __restrict__ Kout, float* __restrict__ Cout) {
    __shared__ float As[8][128];
    __shared__ float Bs[8][128];
    const int tid = threadIdx.x;
    const int tx = tid & 15;         // 0..15 -> col group
    const int ty = tid >> 4;         // 0..15 -> row group
    const int lr = tid >> 1;         // 0..127 load row
    const int lc = (tid & 1) * 4;    // 0 or 4 load col (k)

    const float* Sp = S + ((size_t)(blockIdx.y * 128 + lr)) * DD + lc;
    const float* Tp = T + ((size_t)(blockIdx.x * 128 + lr)) * DD + lc;

    float acc[8][8];
    #pragma unroll
    for (int r = 0; r < 8; r++)
        #pragma unroll
        for (int c = 0; c < 8; c++) acc[r][c] = 0.0f;

    for (int k0 = 0; k0 < DD; k0 += 8) {
        float4 a = *(const float4*)(Sp + k0);
        float4 b = *(const float4*)(Tp + k0);
        As[lc + 0][lr] = a.x; As[lc + 1][lr] = a.y; As[lc + 2][lr] = a.z; As[lc + 3][lr] = a.w;
        Bs[lc + 0][lr] = b.x; Bs[lc + 1][lr] = b.y; Bs[lc + 2][lr] = b.z; Bs[lc + 3][lr] = b.w;
        __syncthreads();
        #pragma unroll
        for (int k = 0; k < 8; k++) {
            float ar[8], br[8];
            #pragma unroll
            for (int r = 0; r < 8; r++) ar[r] = As[k][ty * 8 + r];
            #pragma unroll
            for (int c = 0; c < 8; c++) br[c] = Bs[k][tx * 8 + c];
            #pragma unroll
            for (int r = 0; r < 8; r++)
                #pragma unroll
                for (int c = 0; c < 8; c++)
                    acc[r][c] = fmaf(ar[r], br[c], acc[r][c]);
        }
        __syncthreads();
    }

    const int row0 = blockIdx.y * 128 + ty * 8;
    const int col0 = blockIdx.x * 128 + tx * 8;
    float tn[8];
    #pragma unroll
    for (int c = 0; c < 8; c++) tn[c] = g_tn[col0 + c];

    #pragma unroll
    for (int r = 0; r < 8; r++) {
        float sn = g_sn[row0 + r];
        size_t base = (size_t)(row0 + r) * NN + col0;
        #pragma unroll
        for (int c = 0; c < 8; c++) {
            float sq = sn + tn[c] - 2.0f * acc[r][c];
            float cc = sqrtf(fmaxf(sq, 0.0f));
            float kk = expf(-cc * INV_EPS);
            Cout[base + c] = cc;           // output region is +1 offset -> scalar stores (alignment)
            Kout[base + c] = kk;
            g_Kh[base + c] = __float2half(kk);
        }
    }
}

// ---------------- u[i] = a / (K v + stab): block per row ----------------
__global__ __launch_bounds__(256)
void row_mv_kernel() {
    const int i = blockIdx.x;
    const __half2* Kr = (const __half2*)(g_Kh + (size_t)i * NN);
    float sum = 0.0f;
    #pragma unroll 4
    for (int j2 = threadIdx.x; j2 < NN / 2; j2 += 256) {
        float2 f = __half22float2(Kr[j2]);
        sum = fmaf(f.x, g_v[2 * j2], sum);
        sum = fmaf(f.y, g_v[2 * j2 + 1], sum);
    }
    #pragma unroll
    for (int o = 16; o > 0; o >>= 1) sum += __shfl_down_sync(0xffffffffu, sum, o);
    __shared__ float sh[8];
    if ((threadIdx.x & 31) == 0) sh[threadIdx.x >> 5] = sum;
    __syncthreads();
    if (threadIdx.x == 0) {
        float t = 0.0f;
        #pragma unroll
        for (int w = 0; w < 8; w++) t += sh[w];
        g_u[i] = (1.0f / NN) / (t + STABZ);
    }
}

// ---------------- colpart[chunk][j] = sum_{i in chunk} K[i,j]*u[i] ----------------
// grid (8, 32): 8 col-tiles of 512 cols (256 half2), 32 row-chunks of 128 rows.
__global__ __launch_bounds__(256)
void col_mv_part_kernel() {
    const int j2 = blockIdx.x * 256 + threadIdx.x;   // half2 column index
    const int i0 = blockIdx.y * 128;
    __shared__ float ush[128];
    if (threadIdx.x < 128) ush[threadIdx.x] = g_u[i0 + threadIdx.x];
    __syncthreads();
    float sx = 0.0f, sy = 0.0f;
    const __half2* Kc = (const __half2*)g_Kh;
    #pragma unroll 4
    for (int ii = 0; ii < 128; ii++) {
        float2 f = __half22float2(Kc[(size_t)(i0 + ii) * (NN / 2) + j2]);
        float u = ush[ii];
        sx = fmaf(f.x, u, sx);
        sy = fmaf(f.y, u, sy);
    }
    g_colpart[blockIdx.y * NN + 2 * j2]     = sx;
    g_colpart[blockIdx.y * NN + 2 * j2 + 1] = sy;
}

// ---------------- v[j] = b / (sum_chunks + stab) ----------------
__global__ void col_reduce_kernel() {
    int j = blockIdx.x * 256 + threadIdx.x;
    float s = 0.0f;
    #pragma unroll
    for (int ch = 0; ch < 32; ch++) s += g_colpart[ch * NN + j];
    g_v[j] = (1.0f / NN) / (s + STABZ);
}

// ---------------- coupling = u * K * v (in place over K region) + loss row-partials ----------------
__global__ __launch_bounds__(256)
void final_kernel(float* __restrict__ Kc, const float* __restrict__ Cc) {
    const int i = blockIdx.x;
    const float ui = g_u[i];
    float*       Kr = Kc + (size_t)i * NN;
    const float* Cr = Cc + (size_t)i * NN;
    float lp = 0.0f;
    #pragma unroll 4
    for (int j = threadIdx.x; j < NN; j += 256) {
        float cp = ui * Kr[j] * g_v[j];
        Kr[j] = cp;
        lp = fmaf(cp, Cr[j], lp);
    }
    #pragma unroll
    for (int o = 16; o > 0; o >>= 1) lp += __shfl_down_sync(0xffffffffu, lp, o);
    __shared__ float sh[8];
    if ((threadIdx.x & 31) == 0) sh[threadIdx.x >> 5] = lp;
    __syncthreads();
    if (threadIdx.x == 0) {
        float t = 0.0f;
        #pragma unroll
        for (int w = 0; w < 8; w++) t += sh[w];
        g_losspart[i] = t;
    }
}

// ---------------- deterministic final loss reduction ----------------
__global__ void loss_kernel(float* __restrict__ out) {
    __shared__ float sh[1024];
    float s = 0.0f;
    for (int i = threadIdx.x; i < NN; i += 1024) s += g_losspart[i];
    sh[threadIdx.x] = s;
    __syncthreads();
    for (int o = 512; o > 0; o >>= 1) {
        if (threadIdx.x < o) sh[threadIdx.x] += sh[threadIdx.x + o];
        __syncthreads();
    }
    if (threadIdx.x == 0) out[0] = sh[0] * (1.0f / ((float)NN * (float)NN));
}

extern "C" void kernel_launch(void* const* d_in, const int* in_sizes, int n_in,
                              void* d_out, int out_size) {
    const float* S = (const float*)d_in[0];
    const float* T = (const float*)d_in[1];
    float* out = (float*)d_out;
    // layout: [ loss(1) | coupling(NN*NN) | C(NN*NN) ]
    float* coupling = out + 1;
    float* Cmat     = out + 1 + (size_t)NN * NN;

    norm_kernel<<<dim3(NN, 2), 128>>>(S, T);
    init_v_kernel<<<NN / 256, 256>>>();
    gemm_fused_kernel<<<dim3(32, 32), 256>>>(S, T, coupling, Cmat);

    for (int it = 0; it < 10; it++) {
        row_mv_kernel<<<NN, 256>>>();
        col_mv_part_kernel<<<dim3(8, 32), 256>>>();
        col_reduce_kernel<<<16, 256>>>();
    }

    final_kernel<<<NN, 256>>>(coupling, Cmat);
    loss_kernel<<<1, 1024>>>(out);
}

// round 5
// speedup vs baseline: 1.2440x; 1.2440x over previous
#include <cuda_runtime.h>
#include <cuda_fp16.h>
#include <cuda_bf16.h>
#include <math.h>
#include <stdint.h>

#define NN 4096
#define DD 512
#define INV_EPS 0.125f
#define STABZ 1e-8f

// ---- device scratch (no allocations allowed) ----
__device__ __nv_bfloat16 g_Sh[(size_t)NN * DD];
__device__ __nv_bfloat16 g_Sl[(size_t)NN * DD];
__device__ __nv_bfloat16 g_Th[(size_t)NN * DD];
__device__ __nv_bfloat16 g_Tl[(size_t)NN * DD];
__device__ float  g_u[NN];
__device__ float  g_v[NN];
__device__ float  g_sn[NN];
__device__ float  g_tn[NN];
__device__ __half g_Kh[(size_t)NN * NN];     // 32 MB fp16 Gibbs kernel for Sinkhorn matvecs
__device__ float  g_colpart[32 * NN];
__device__ float  g_losspart[NN];

// ================= helpers =================
__device__ __forceinline__ uint32_t s2u(const void* p) {
    uint32_t a;
    asm("{ .reg .u64 t; cvta.to.shared.u64 t, %1; cvt.u32.u64 %0, t; }" : "=r"(a) : "l"(p));
    return a;
}
#define SW128(o) ((o) ^ (((o) >> 3) & 0x70))

__device__ __forceinline__ void cp16(uint32_t dst, const void* src) {
    asm volatile("cp.async.cg.shared.global [%0], [%1], 16;" :: "r"(dst), "l"(src));
}

__device__ __forceinline__ void ldm4(uint32_t& r0, uint32_t& r1, uint32_t& r2, uint32_t& r3,
                                     uint32_t addr) {
    asm volatile("ldmatrix.sync.aligned.m8n8.x4.shared.b16 {%0,%1,%2,%3}, [%4];"
                 : "=r"(r0), "=r"(r1), "=r"(r2), "=r"(r3) : "r"(addr));
}

__device__ __forceinline__ void mma16816(float* c, const uint32_t* a, const uint32_t* b) {
    asm volatile(
        "mma.sync.aligned.m16n8k16.row.col.f32.bf16.bf16.f32 "
        "{%0,%1,%2,%3}, {%4,%5,%6,%7}, {%8,%9}, {%0,%1,%2,%3};"
        : "+f"(c[0]), "+f"(c[1]), "+f"(c[2]), "+f"(c[3])
        : "r"(a[0]), "r"(a[1]), "r"(a[2]), "r"(a[3]), "r"(b[0]), "r"(b[1]));
}

// ================= small kernels =================
__global__ void norm_kernel(const float* __restrict__ S, const float* __restrict__ T) {
    const float* src = blockIdx.y ? T : S;
    float*       dst = blockIdx.y ? g_tn : g_sn;
    int row = blockIdx.x;
    const float4* p = (const float4*)(src + (size_t)row * DD);
    float4 x = p[threadIdx.x];
    float s = x.x * x.x + x.y * x.y + x.z * x.z + x.w * x.w;
    #pragma unroll
    for (int o = 16; o > 0; o >>= 1) s += __shfl_down_sync(0xffffffffu, s, o);
    __shared__ float sh[4];
    if ((threadIdx.x & 31) == 0) sh[threadIdx.x >> 5] = s;
    __syncthreads();
    if (threadIdx.x == 0) dst[row] = sh[0] + sh[1] + sh[2] + sh[3];
}

// split fp32 -> bf16 hi + bf16 lo (residual)
__global__ void cvt_kernel(const float* __restrict__ S, const float* __restrict__ T) {
    const float* src = blockIdx.y ? T : S;
    __nv_bfloat16* hi = blockIdx.y ? g_Th : g_Sh;
    __nv_bfloat16* lo = blockIdx.y ? g_Tl : g_Sl;
    int base = (blockIdx.x * 256 + threadIdx.x) * 4;
    float4 x = *(const float4*)(src + base);
    __nv_bfloat16 h0 = __float2bfloat16_rn(x.x);
    __nv_bfloat16 h1 = __float2bfloat16_rn(x.y);
    __nv_bfloat16 h2 = __float2bfloat16_rn(x.z);
    __nv_bfloat16 h3 = __float2bfloat16_rn(x.w);
    __nv_bfloat16 l0 = __float2bfloat16_rn(x.x - __bfloat162float(h0));
    __nv_bfloat16 l1 = __float2bfloat16_rn(x.y - __bfloat162float(h1));
    __nv_bfloat16 l2 = __float2bfloat16_rn(x.z - __bfloat162float(h2));
    __nv_bfloat16 l3 = __float2bfloat16_rn(x.w - __bfloat162float(h3));
    *(__nv_bfloat162*)(hi + base)     = __halves2bfloat162(h0, h1);
    *(__nv_bfloat162*)(hi + base + 2) = __halves2bfloat162(h2, h3);
    *(__nv_bfloat162*)(lo + base)     = __halves2bfloat162(l0, l1);
    *(__nv_bfloat162*)(lo + base + 2) = __halves2bfloat162(l2, l3);
}

__global__ void init_v_kernel() {
    int i = blockIdx.x * 256 + threadIdx.x;
    if (i < NN) g_v[i] = 1.0f;
}

// ================= mma.sync GEMM + fused epilogue =================
// D = S@T^T via 3 bf16 products (hh + lh + hl) -> ~fp32 precision.
// C = sqrt(max(sn+tn-2D,0)) -> Cout (fp32); Kh = fp16(exp(-C/8)).
// 128x128 CTA tile, BK=64, 2-stage cp.async pipeline, 8 warps (32x64 each).
#define TILE_B 16384                  // one 128x64 bf16 tile
#define STAGE_B (4 * TILE_B)          // Ah, Bh, Al, Bl
#define SMEM_DYN (2 * STAGE_B)        // 131072

__global__ __launch_bounds__(256, 1)
void gemm_kernel(float* __restrict__ Cout) {
    extern __shared__ char smem[];
    const uint32_t sb = s2u(smem);
    const int tid = threadIdx.x, wid = tid >> 5, lid = tid & 31;
    const int wr = wid & 3, wc = wid >> 2;       // warp tile: rows wr*32, cols wc*64
    const int row0 = blockIdx.y * 128;
    const int col0 = blockIdx.x * 128;

    const __nv_bfloat16* gA[4];
    gA[0] = g_Sh + (size_t)row0 * DD;
    gA[1] = g_Th + (size_t)col0 * DD;
    gA[2] = g_Sl + (size_t)row0 * DD;
    gA[3] = g_Tl + (size_t)col0 * DD;

    // per-thread load coords (4 chunks of 16B per tile)
    const int lrow[4] = { (tid + 0) >> 3, (tid + 256) >> 3, (tid + 512) >> 3, (tid + 768) >> 3 };
    const int lcb = tid & 7;

    // ldmatrix per-lane address components
    const int mi = lid >> 3, r8 = lid & 7;
    const int a_row = wr * 32 + (mi & 1) * 8 + r8;        // + m*16
    const int a_cb  = (mi >> 1) * 16;                     // + ks*32
    const int b_row = wc * 64 + (mi & 2) * 4 + r8;        // + g*16
    const int b_cb  = (mi & 1) * 16;                      // + ks*32

    float acc[2][8][4];
    #pragma unroll
    for (int m = 0; m < 2; m++)
        #pragma unroll
        for (int n = 0; n < 8; n++)
            #pragma unroll
            for (int q = 0; q < 4; q++) acc[m][n][q] = 0.0f;

    // prologue: load stage 0 (chunk 0)
    #pragma unroll
    for (int t4 = 0; t4 < 4; t4++) {
        uint32_t tb = sb + t4 * TILE_B;
        const __nv_bfloat16* g = gA[t4];
        #pragma unroll
        for (int p = 0; p < 4; p++)
            cp16(tb + SW128((uint32_t)(lrow[p] * 128 + lcb * 16)),
                 (const void*)(g + (size_t)lrow[p] * DD + lcb * 8));
    }
    asm volatile("cp.async.commit_group;");

    for (int ch = 0; ch < 8; ch++) {
        const uint32_t cur = sb + (ch & 1) * STAGE_B;
        if (ch < 7) {
            const uint32_t nxt = sb + ((ch + 1) & 1) * STAGE_B;
            #pragma unroll
            for (int t4 = 0; t4 < 4; t4++) {
                uint32_t tb = nxt + t4 * TILE_B;
                const __nv_bfloat16* g = gA[t4] + (ch + 1) * 64;
                #pragma unroll
                for (int p = 0; p < 4; p++)
                    cp16(tb + SW128((uint32_t)(lrow[p] * 128 + lcb * 16)),
                         (const void*)(g + (size_t)lrow[p] * DD + lcb * 8));
            }
            asm volatile("cp.async.commit_group;");
            asm volatile("cp.async.wait_group 1;" ::: "memory");
        } else {
            asm volatile("cp.async.wait_group 0;" ::: "memory");
        }
        __syncthreads();

        const uint32_t tAh = cur, tBh = cur + TILE_B, tAl = cur + 2 * TILE_B, tBl = cur + 3 * TILE_B;
        #pragma unroll
        for (int ks = 0; ks < 4; ks++) {
            const int cb = ks * 32;
            uint32_t ah[2][4], al[2][4], bh[8][2], bl[8][2];
            #pragma unroll
            for (int m = 0; m < 2; m++) {
                uint32_t off = SW128((uint32_t)((a_row + m * 16) * 128 + a_cb + cb));
                ldm4(ah[m][0], ah[m][1], ah[m][2], ah[m][3], tAh + off);
                ldm4(al[m][0], al[m][1], al[m][2], al[m][3], tAl + off);
            }
            #pragma unroll
            for (int g = 0; g < 4; g++) {
                uint32_t off = SW128((uint32_t)((b_row + g * 16) * 128 + b_cb + cb));
                ldm4(bh[2 * g][0], bh[2 * g][1], bh[2 * g + 1][0], bh[2 * g + 1][1], tBh + off);
                ldm4(bl[2 * g][0], bl[2 * g][1], bl[2 * g + 1][0], bl[2 * g + 1][1], tBl + off);
            }
            #pragma unroll
            for (int m = 0; m < 2; m++)
                #pragma unroll
                for (int n = 0; n < 8; n++) {
                    mma16816(acc[m][n], ah[m], bh[n]);
                    mma16816(acc[m][n], al[m], bh[n]);
                    mma16816(acc[m][n], ah[m], bl[n]);
                }
        }
        __syncthreads();
    }

    // ---- epilogue: convert to C, stage in smem, coalesced global stores ----
    float* sm = (float*)smem;    // 128 x 129 fp32
    const int qr = lid >> 2, qc = lid & 3;
    #pragma unroll
    for (int m = 0; m < 2; m++) {
        const int rb = wr * 32 + m * 16 + qr;
        const float sn0 = g_sn[row0 + rb];
        const float sn1 = g_sn[row0 + rb + 8];
        #pragma unroll
        for (int n = 0; n < 8; n++) {
            const int cl = wc * 64 + n * 8 + 2 * qc;
            const float tn0 = __ldg(&g_tn[col0 + cl]);
            const float tn1 = __ldg(&g_tn[col0 + cl + 1]);
            sm[rb * 129 + cl]           = sqrtf(fmaxf(sn0 + tn0 - 2.0f * acc[m][n][0], 0.0f));
            sm[rb * 129 + cl + 1]       = sqrtf(fmaxf(sn0 + tn1 - 2.0f * acc[m][n][1], 0.0f));
            sm[(rb + 8) * 129 + cl]     = sqrtf(fmaxf(sn1 + tn0 - 2.0f * acc[m][n][2], 0.0f));
            sm[(rb + 8) * 129 + cl + 1] = sqrtf(fmaxf(sn1 + tn1 - 2.0f * acc[m][n][3], 0.0f));
        }
    }
    __syncthreads();

    #pragma unroll 4
    for (int it = 0; it < 64; it++) {
        int lin = it * 256 + tid;
        int r = lin >> 7, c = lin & 127;
        Cout[(size_t)(row0 + r) * NN + col0 + c] = sm[r * 129 + c];
    }
    __half2* Kh2 = (__half2*)g_Kh;
    #pragma unroll 4
    for (int it = 0; it < 32; it++) {
        int lin = it * 256 + tid;
        int r = lin >> 6, c2 = lin & 63;
        float a = sm[r * 129 + 2 * c2];
        float b = sm[r * 129 + 2 * c2 + 1];
        Kh2[((size_t)(row0 + r) * NN + col0) / 2 + c2] =
            __floats2half2_rn(__expf(-a * INV_EPS), __expf(-b * INV_EPS));
    }
}

// ================= Sinkhorn =================
__global__ __launch_bounds__(256)
void row_mv_kernel() {
    const int i = blockIdx.x;
    const uint4*  Kr = (const uint4*)(g_Kh + (size_t)i * NN);
    const float4* V4 = (const float4*)g_v;
    float sum = 0.0f;
    #pragma unroll
    for (int p = 0; p < 2; p++) {
        int j = threadIdx.x + p * 256;
        uint4 q = Kr[j];
        float4 v0 = V4[2 * j], v1 = V4[2 * j + 1];
        float2 f0 = __half22float2(*(const __half2*)&q.x);
        float2 f1 = __half22float2(*(const __half2*)&q.y);
        float2 f2 = __half22float2(*(const __half2*)&q.z);
        float2 f3 = __half22float2(*(const __half2*)&q.w);
        sum = fmaf(f0.x, v0.x, sum); sum = fmaf(f0.y, v0.y, sum);
        sum = fmaf(f1.x, v0.z, sum); sum = fmaf(f1.y, v0.w, sum);
        sum = fmaf(f2.x, v1.x, sum); sum = fmaf(f2.y, v1.y, sum);
        sum = fmaf(f3.x, v1.z, sum); sum = fmaf(f3.y, v1.w, sum);
    }
    #pragma unroll
    for (int o = 16; o > 0; o >>= 1) sum += __shfl_down_sync(0xffffffffu, sum, o);
    __shared__ float sh[8];
    if ((threadIdx.x & 31) == 0) sh[threadIdx.x >> 5] = sum;
    __syncthreads();
    if (threadIdx.x == 0) {
        float t = 0.0f;
        #pragma unroll
        for (int w = 0; w < 8; w++) t += sh[w];
        g_u[i] = (1.0f / NN) / (t + STABZ);
    }
}

__global__ __launch_bounds__(256)
void col_mv_part_kernel() {
    const int cb = blockIdx.x * 256 + threadIdx.x;   // uint4 index within row (0..511)
    const int i0 = blockIdx.y * 128;
    __shared__ float ush[128];
    if (threadIdx.x < 128) ush[threadIdx.x] = g_u[i0 + threadIdx.x];
    __syncthreads();
    float a0 = 0, a1 = 0, a2 = 0, a3 = 0, a4 = 0, a5 = 0, a6 = 0, a7 = 0;
    #pragma unroll 4
    for (int ii = 0; ii < 128; ii++) {
        uint4 q = *(const uint4*)(g_Kh + (size_t)(i0 + ii) * NN + cb * 8);
        float u = ush[ii];
        float2 f0 = __half22float2(*(const __half2*)&q.x);
        float2 f1 = __half22float2(*(const __half2*)&q.y);
        float2 f2 = __half22float2(*(const __half2*)&q.z);
        float2 f3 = __half22float2(*(const __half2*)&q.w);
        a0 = fmaf(f0.x, u, a0); a1 = fmaf(f0.y, u, a1);
        a2 = fmaf(f1.x, u, a2); a3 = fmaf(f1.y, u, a3);
        a4 = fmaf(f2.x, u, a4); a5 = fmaf(f2.y, u, a5);
        a6 = fmaf(f3.x, u, a6); a7 = fmaf(f3.y, u, a7);
    }
    float4* P = (float4*)(g_colpart + blockIdx.y * NN + cb * 8);
    P[0] = make_float4(a0, a1, a2, a3);
    P[1] = make_float4(a4, a5, a6, a7);
}

__global__ void col_reduce_kernel() {
    int j = blockIdx.x * 256 + threadIdx.x;
    float s = 0.0f;
    #pragma unroll
    for (int ch = 0; ch < 32; ch++) s += g_colpart[ch * NN + j];
    g_v[j] = (1.0f / NN) / (s + STABZ);
}

// ================= final: coupling = u*exp(-C/8)*v, loss partials =================
__global__ __launch_bounds__(256)
void final_kernel(float* __restrict__ coup, const float* __restrict__ Cc) {
    const int i = blockIdx.x;
    const float ui = g_u[i];
    const float* Cr = Cc + (size_t)i * NN;
    float*       Or = coup + (size_t)i * NN;
    float lp = 0.0f;
    #pragma unroll 4
    for (int j = threadIdx.x; j < NN; j += 256) {
        float c = Cr[j];
        float cp = ui * expf(-c * INV_EPS) * g_v[j];
        Or[j] = cp;
        lp = fmaf(cp, c, lp);
    }
    #pragma unroll
    for (int o = 16; o > 0; o >>= 1) lp += __shfl_down_sync(0xffffffffu, lp, o);
    __shared__ float sh[8];
    if ((threadIdx.x & 31) == 0) sh[threadIdx.x >> 5] = lp;
    __syncthreads();
    if (threadIdx.x == 0) {
        float t = 0.0f;
        #pragma unroll
        for (int w = 0; w < 8; w++) t += sh[w];
        g_losspart[i] = t;
    }
}

__global__ void loss_kernel(float* __restrict__ out) {
    __shared__ float sh[1024];
    float s = 0.0f;
    for (int i = threadIdx.x; i < NN; i += 1024) s += g_losspart[i];
    sh[threadIdx.x] = s;
    __syncthreads();
    for (int o = 512; o > 0; o >>= 1) {
        if (threadIdx.x < o) sh[threadIdx.x] += sh[threadIdx.x + o];
        __syncthreads();
    }
    if (threadIdx.x == 0) out[0] = sh[0] * (1.0f / ((float)NN * (float)NN));
}

extern "C" void kernel_launch(void* const* d_in, const int* in_sizes, int n_in,
                              void* d_out, int out_size) {
    const float* S = (const float*)d_in[0];
    const float* T = (const float*)d_in[1];
    float* out = (float*)d_out;
    // layout: [ loss(1) | coupling(NN*NN) | C(NN*NN) ]
    float* coupling = out + 1;
    float* Cmat     = out + 1 + (size_t)NN * NN;

    cudaFuncSetAttribute(gemm_kernel, cudaFuncAttributeMaxDynamicSharedMemorySize, SMEM_DYN);

    norm_kernel<<<dim3(NN, 2), 128>>>(S, T);
    cvt_kernel<<<dim3(2048, 2), 256>>>(S, T);
    init_v_kernel<<<16, 256>>>();
    gemm_kernel<<<dim3(32, 32), 256, SMEM_DYN>>>(Cmat);

    for (int it = 0; it < 10; it++) {
        row_mv_kernel<<<NN, 256>>>();
        col_mv_part_kernel<<<dim3(2, 32), 256>>>();
        col_reduce_kernel<<<16, 256>>>();
    }

    final_kernel<<<NN, 256>>>(coupling, Cmat);
    loss_kernel<<<1, 1024>>>(out);
}

// round 9
// speedup vs baseline: 2.0370x; 1.6374x over previous
#include <cuda_runtime.h>
#include <cuda_fp16.h>
#include <cuda_bf16.h>
#include <math.h>
#include <stdint.h>

#define NN 4096
#define DD 512
#define INV_EPS 0.125f
#define STABZ 1e-8f

// ---- device scratch (no allocations allowed) ----
__device__ __nv_bfloat16 g_Sh[(size_t)NN * DD];
__device__ __nv_bfloat16 g_Sl[(size_t)NN * DD];
__device__ __nv_bfloat16 g_Th[(size_t)NN * DD];
__device__ __nv_bfloat16 g_Tl[(size_t)NN * DD];
__device__ float  g_u[NN];
__device__ float  g_v[NN];
__device__ float  g_sn[NN];
__device__ float  g_tn[NN];
__device__ __half g_Kh[(size_t)NN * NN];     // 32 MB fp16 Gibbs kernel for Sinkhorn matvecs
__device__ float  g_colpart[128 * NN];
__device__ float  g_losspart[NN];

// ================= helpers =================
__device__ __forceinline__ uint32_t s2u(const void* p) {
    uint32_t a;
    asm("{ .reg .u64 t; cvta.to.shared.u64 t, %1; cvt.u32.u64 %0, t; }" : "=r"(a) : "l"(p));
    return a;
}
#define SW128(o) ((o) ^ (((o) >> 3) & 0x70))

__device__ __forceinline__ void cp16(uint32_t dst, const void* src) {
    asm volatile("cp.async.cg.shared.global [%0], [%1], 16;" :: "r"(dst), "l"(src));
}

__device__ __forceinline__ void ldm4(uint32_t& r0, uint32_t& r1, uint32_t& r2, uint32_t& r3,
                                     uint32_t addr) {
    asm volatile("ldmatrix.sync.aligned.m8n8.x4.shared.b16 {%0,%1,%2,%3}, [%4];"
                 : "=r"(r0), "=r"(r1), "=r"(r2), "=r"(r3) : "r"(addr));
}

__device__ __forceinline__ void mma16816(float* c, const uint32_t* a, const uint32_t* b) {
    asm volatile(
        "mma.sync.aligned.m16n8k16.row.col.f32.bf16.bf16.f32 "
        "{%0,%1,%2,%3}, {%4,%5,%6,%7}, {%8,%9}, {%0,%1,%2,%3};"
        : "+f"(c[0]), "+f"(c[1]), "+f"(c[2]), "+f"(c[3])
        : "r"(a[0]), "r"(a[1]), "r"(a[2]), "r"(a[3]), "r"(b[0]), "r"(b[1]));
}

// ================= small kernels =================
__global__ void norm_kernel(const float* __restrict__ S, const float* __restrict__ T) {
    const float* src = blockIdx.y ? T : S;
    float*       dst = blockIdx.y ? g_tn : g_sn;
    int row = blockIdx.x;
    const float4* p = (const float4*)(src + (size_t)row * DD);
    float4 x = p[threadIdx.x];
    float s = x.x * x.x + x.y * x.y + x.z * x.z + x.w * x.w;
    #pragma unroll
    for (int o = 16; o > 0; o >>= 1) s += __shfl_down_sync(0xffffffffu, s, o);
    __shared__ float sh[4];
    if ((threadIdx.x & 31) == 0) sh[threadIdx.x >> 5] = s;
    __syncthreads();
    if (threadIdx.x == 0) dst[row] = sh[0] + sh[1] + sh[2] + sh[3];
}

// split fp32 -> bf16 hi + bf16 lo (residual)
__global__ void cvt_kernel(const float* __restrict__ S, const float* __restrict__ T) {
    const float* src = blockIdx.y ? T : S;
    __nv_bfloat16* hi = blockIdx.y ? g_Th : g_Sh;
    __nv_bfloat16* lo = blockIdx.y ? g_Tl : g_Sl;
    int base = (blockIdx.x * 256 + threadIdx.x) * 4;
    float4 x = *(const float4*)(src + base);
    __nv_bfloat16 h0 = __float2bfloat16_rn(x.x);
    __nv_bfloat16 h1 = __float2bfloat16_rn(x.y);
    __nv_bfloat16 h2 = __float2bfloat16_rn(x.z);
    __nv_bfloat16 h3 = __float2bfloat16_rn(x.w);
    __nv_bfloat16 l0 = __float2bfloat16_rn(x.x - __bfloat162float(h0));
    __nv_bfloat16 l1 = __float2bfloat16_rn(x.y - __bfloat162float(h1));
    __nv_bfloat16 l2 = __float2bfloat16_rn(x.z - __bfloat162float(h2));
    __nv_bfloat16 l3 = __float2bfloat16_rn(x.w - __bfloat162float(h3));
    *(__nv_bfloat162*)(hi + base)     = __halves2bfloat162(h0, h1);
    *(__nv_bfloat162*)(hi + base + 2) = __halves2bfloat162(h2, h3);
    *(__nv_bfloat162*)(lo + base)     = __halves2bfloat162(l0, l1);
    *(__nv_bfloat162*)(lo + base + 2) = __halves2bfloat162(l2, l3);
}

__global__ void init_v_kernel() {
    int i = blockIdx.x * 256 + threadIdx.x;
    if (i < NN) g_v[i] = 1.0f;
}

// ================= mma.sync GEMM + fused epilogue =================
// D = S@T^T via 3 bf16 products (hh + lh + hl) -> ~fp32 precision.
// C = sqrt(max(sn+tn-2D,0)) -> Cout (fp32); Kh = fp16(exp(-C/8)).
// 128x128 CTA tile, BK=64, 2-stage cp.async pipeline, 16 warps (32x32 each).
#define TILE_B 16384                  // one 128x64 bf16 tile
#define STAGE_B (4 * TILE_B)          // Ah, Bh, Al, Bl
#define SMEM_DYN (2 * STAGE_B)        // 131072

__global__ __launch_bounds__(512, 1)
void gemm_kernel(float* __restrict__ Cout) {
    extern __shared__ char smem[];
    const uint32_t sb = s2u(smem);
    const int tid = threadIdx.x, wid = tid >> 5, lid = tid & 31;
    const int wr = wid & 3, wc = wid >> 2;       // warp tile: rows wr*32, cols wc*32
    const int row0 = blockIdx.y * 128;
    const int col0 = blockIdx.x * 128;

    const __nv_bfloat16* gA[4];
    gA[0] = g_Sh + (size_t)row0 * DD;
    gA[1] = g_Th + (size_t)col0 * DD;
    gA[2] = g_Sl + (size_t)row0 * DD;
    gA[3] = g_Tl + (size_t)col0 * DD;

    // per-thread load coords: each tile = 1024 chunks of 16B; 512 threads -> 2 per tile
    const int lrow0 = tid >> 3, lrow1 = (tid + 512) >> 3;
    const int lcb = tid & 7;

    // ldmatrix per-lane address components (validated mapping)
    const int mi = lid >> 3, r8 = lid & 7;
    const int a_row = wr * 32 + (mi & 1) * 8 + r8;        // + m*16
    const int a_cb  = (mi >> 1) * 16;                     // + ks*32
    const int b_row = wc * 32 + (mi & 2) * 4 + r8;        // + g*16
    const int b_cb  = (mi & 1) * 16;                      // + ks*32

    float acc[2][4][4];
    #pragma unroll
    for (int m = 0; m < 2; m++)
        #pragma unroll
        for (int n = 0; n < 4; n++)
            #pragma unroll
            for (int q = 0; q < 4; q++) acc[m][n][q] = 0.0f;

    // prologue: load stage 0 (chunk 0)
    #pragma unroll
    for (int t4 = 0; t4 < 4; t4++) {
        uint32_t tb = sb + t4 * TILE_B;
        const __nv_bfloat16* g = gA[t4];
        cp16(tb + SW128((uint32_t)(lrow0 * 128 + lcb * 16)),
             (const void*)(g + (size_t)lrow0 * DD + lcb * 8));
        cp16(tb + SW128((uint32_t)(lrow1 * 128 + lcb * 16)),
             (const void*)(g + (size_t)lrow1 * DD + lcb * 8));
    }
    asm volatile("cp.async.commit_group;");

    for (int ch = 0; ch < 8; ch++) {
        const uint32_t cur = sb + (ch & 1) * STAGE_B;
        if (ch < 7) {
            const uint32_t nxt = sb + ((ch + 1) & 1) * STAGE_B;
            #pragma unroll
            for (int t4 = 0; t4 < 4; t4++) {
                uint32_t tb = nxt + t4 * TILE_B;
                const __nv_bfloat16* g = gA[t4] + (ch + 1) * 64;
                cp16(tb + SW128((uint32_t)(lrow0 * 128 + lcb * 16)),
                     (const void*)(g + (size_t)lrow0 * DD + lcb * 8));
                cp16(tb + SW128((uint32_t)(lrow1 * 128 + lcb * 16)),
                     (const void*)(g + (size_t)lrow1 * DD + lcb * 8));
            }
            asm volatile("cp.async.commit_group;");
            asm volatile("cp.async.wait_group 1;" ::: "memory");
        } else {
            asm volatile("cp.async.wait_group 0;" ::: "memory");
        }
        __syncthreads();

        const uint32_t tAh = cur, tBh = cur + TILE_B, tAl = cur + 2 * TILE_B, tBl = cur + 3 * TILE_B;
        #pragma unroll
        for (int ks = 0; ks < 4; ks++) {
            const int cb = ks * 32;
            uint32_t ah[2][4], al[2][4], bh[4][2], bl[4][2];
            #pragma unroll
            for (int m = 0; m < 2; m++) {
                uint32_t off = SW128((uint32_t)((a_row + m * 16) * 128 + a_cb + cb));
                ldm4(ah[m][0], ah[m][1], ah[m][2], ah[m][3], tAh + off);
                ldm4(al[m][0], al[m][1], al[m][2], al[m][3], tAl + off);
            }
            #pragma unroll
            for (int g = 0; g < 2; g++) {
                uint32_t off = SW128((uint32_t)((b_row + g * 16) * 128 + b_cb + cb));
                ldm4(bh[2 * g][0], bh[2 * g][1], bh[2 * g + 1][0], bh[2 * g + 1][1], tBh + off);
                ldm4(bl[2 * g][0], bl[2 * g][1], bl[2 * g + 1][0], bl[2 * g + 1][1], tBl + off);
            }
            #pragma unroll
            for (int m = 0; m < 2; m++)
                #pragma unroll
                for (int n = 0; n < 4; n++) {
                    mma16816(acc[m][n], ah[m], bh[n]);
                    mma16816(acc[m][n], al[m], bh[n]);
                    mma16816(acc[m][n], ah[m], bl[n]);
                }
        }
        __syncthreads();
    }

    // ---- epilogue: convert to C, stage in smem, coalesced global stores ----
    float* sm = (float*)smem;    // 128 x 129 fp32
    const int qr = lid >> 2, qc = lid & 3;
    #pragma unroll
    for (int m = 0; m < 2; m++) {
        const int rb = wr * 32 + m * 16 + qr;
        const float sn0 = g_sn[row0 + rb];
        const float sn1 = g_sn[row0 + rb + 8];
        #pragma unroll
        for (int n = 0; n < 4; n++) {
            const int cl = wc * 32 + n * 8 + 2 * qc;
            const float tn0 = __ldg(&g_tn[col0 + cl]);
            const float tn1 = __ldg(&g_tn[col0 + cl + 1]);
            sm[rb * 129 + cl]           = sqrtf(fmaxf(sn0 + tn0 - 2.0f * acc[m][n][0], 0.0f));
            sm[rb * 129 + cl + 1]       = sqrtf(fmaxf(sn0 + tn1 - 2.0f * acc[m][n][1], 0.0f));
            sm[(rb + 8) * 129 + cl]     = sqrtf(fmaxf(sn1 + tn0 - 2.0f * acc[m][n][2], 0.0f));
            sm[(rb + 8) * 129 + cl + 1] = sqrtf(fmaxf(sn1 + tn1 - 2.0f * acc[m][n][3], 0.0f));
        }
    }
    __syncthreads();

    #pragma unroll 4
    for (int it = 0; it < 32; it++) {
        int lin = it * 512 + tid;
        int r = lin >> 7, c = lin & 127;
        Cout[(size_t)(row0 + r) * NN + col0 + c] = sm[r * 129 + c];
    }
    __half2* Kh2 = (__half2*)g_Kh;
    #pragma unroll 4
    for (int it = 0; it < 16; it++) {
        int lin = it * 512 + tid;
        int r = lin >> 6, c2 = lin & 63;
        float a = sm[r * 129 + 2 * c2];
        float b = sm[r * 129 + 2 * c2 + 1];
        Kh2[((size_t)(row0 + r) * NN + col0) / 2 + c2] =
            __floats2half2_rn(__expf(-a * INV_EPS), __expf(-b * INV_EPS));
    }
}

// ================= Sinkhorn =================
__global__ __launch_bounds__(256)
void row_mv_kernel() {
    const int i = blockIdx.x;
    const uint4*  Kr = (const uint4*)(g_Kh + (size_t)i * NN);
    const float4* V4 = (const float4*)g_v;
    float sum = 0.0f;
    #pragma unroll
    for (int p = 0; p < 2; p++) {
        int j = threadIdx.x + p * 256;
        uint4 q = Kr[j];
        float4 v0 = V4[2 * j], v1 = V4[2 * j + 1];
        float2 f0 = __half22float2(*(const __half2*)&q.x);
        float2 f1 = __half22float2(*(const __half2*)&q.y);
        float2 f2 = __half22float2(*(const __half2*)&q.z);
        float2 f3 = __half22float2(*(const __half2*)&q.w);
        sum = fmaf(f0.x, v0.x, sum); sum = fmaf(f0.y, v0.y, sum);
        sum = fmaf(f1.x, v0.z, sum); sum = fmaf(f1.y, v0.w, sum);
        sum = fmaf(f2.x, v1.x, sum); sum = fmaf(f2.y, v1.y, sum);
        sum = fmaf(f3.x, v1.z, sum); sum = fmaf(f3.y, v1.w, sum);
    }
    #pragma unroll
    for (int o = 16; o > 0; o >>= 1) sum += __shfl_down_sync(0xffffffffu, sum, o);
    __shared__ float sh[8];
    if ((threadIdx.x & 31) == 0) sh[threadIdx.x >> 5] = sum;
    __syncthreads();
    if (threadIdx.x == 0) {
        float t = 0.0f;
        #pragma unroll
        for (int w = 0; w < 8; w++) t += sh[w];
        g_u[i] = (1.0f / NN) / (t + STABZ);
    }
}

// partials over 32-row chunks: grid (2, 128) = 256 blocks
__global__ __launch_bounds__(256)
void col_mv_part_kernel() {
    const int cb = blockIdx.x * 256 + threadIdx.x;   // uint4 index within row (0..511)
    const int i0 = blockIdx.y * 32;
    __shared__ float ush[32];
    if (threadIdx.x < 32) ush[threadIdx.x] = g_u[i0 + threadIdx.x];
    __syncthreads();
    float a0 = 0, a1 = 0, a2 = 0, a3 = 0, a4 = 0, a5 = 0, a6 = 0, a7 = 0;
    #pragma unroll 8
    for (int ii = 0; ii < 32; ii++) {
        uint4 q = *(const uint4*)(g_Kh + (size_t)(i0 + ii) * NN + cb * 8);
        float u = ush[ii];
        float2 f0 = __half22float2(*(const __half2*)&q.x);
        float2 f1 = __half22float2(*(const __half2*)&q.y);
        float2 f2 = __half22float2(*(const __half2*)&q.z);
        float2 f3 = __half22float2(*(const __half2*)&q.w);
        a0 = fmaf(f0.x, u, a0); a1 = fmaf(f0.y, u, a1);
        a2 = fmaf(f1.x, u, a2); a3 = fmaf(f1.y, u, a3);
        a4 = fmaf(f2.x, u, a4); a5 = fmaf(f2.y, u, a5);
        a6 = fmaf(f3.x, u, a6); a7 = fmaf(f3.y, u, a7);
    }
    float4* P = (float4*)(g_colpart + blockIdx.y * NN + cb * 8);
    P[0] = make_float4(a0, a1, a2, a3);
    P[1] = make_float4(a4, a5, a6, a7);
}

__global__ void col_reduce_kernel() {
    int j = blockIdx.x * 256 + threadIdx.x;
    float s = 0.0f;
    #pragma unroll 8
    for (int ch = 0; ch < 128; ch++) s += g_colpart[ch * NN + j];
    g_v[j] = (1.0f / NN) / (s + STABZ);
}

// ================= final: coupling = u*exp(-C/8)*v, loss partials =================
// NOTE: coup/Cc are offset by +1 float from the 16B-aligned buffer base, so all
// accesses here must stay 4-byte (scalar) to avoid misaligned 128-bit traps.
__global__ __launch_bounds__(256)
void final_kernel(float* __restrict__ coup, const float* __restrict__ Cc) {
    const int i = blockIdx.x;
    const float ui = g_u[i];
    const float* Cr = Cc + (size_t)i * NN;
    float*       Or = coup + (size_t)i * NN;
    float lp = 0.0f;
    #pragma unroll
    for (int p = 0; p < 16; p++) {
        int j = threadIdx.x + p * 256;
        float c = Cr[j];
        float cp = ui * __expf(-c * INV_EPS) * g_v[j];
        Or[j] = cp;
        lp = fmaf(cp, c, lp);
    }
    #pragma unroll
    for (int o = 16; o > 0; o >>= 1) lp += __shfl_down_sync(0xffffffffu, lp, o);
    __shared__ float sh[8];
    if ((threadIdx.x & 31) == 0) sh[threadIdx.x >> 5] = lp;
    __syncthreads();
    if (threadIdx.x == 0) {
        float t = 0.0f;
        #pragma unroll
        for (int w = 0; w < 8; w++) t += sh[w];
        g_losspart[i] = t;
    }
}

__global__ void loss_kernel(float* __restrict__ out) {
    __shared__ float sh[1024];
    float s = 0.0f;
    for (int i = threadIdx.x; i < NN; i += 1024) s += g_losspart[i];
    sh[threadIdx.x] = s;
    __syncthreads();
    for (int o = 512; o > 0; o >>= 1) {
        if (threadIdx.x < o) sh[threadIdx.x] += sh[threadIdx.x + o];
        __syncthreads();
    }
    if (threadIdx.x == 0) out[0] = sh[0] * (1.0f / ((float)NN * (float)NN));
}

extern "C" void kernel_launch(void* const* d_in, const int* in_sizes, int n_in,
                              void* d_out, int out_size) {
    const float* S = (const float*)d_in[0];
    const float* T = (const float*)d_in[1];
    float* out = (float*)d_out;
    // layout: [ loss(1) | coupling(NN*NN) | C(NN*NN) ]
    float* coupling = out + 1;
    float* Cmat     = out + 1 + (size_t)NN * NN;

    cudaFuncSetAttribute(gemm_kernel, cudaFuncAttributeMaxDynamicSharedMemorySize, SMEM_DYN);

    norm_kernel<<<dim3(NN, 2), 128>>>(S, T);
    cvt_kernel<<<dim3(2048, 2), 256>>>(S, T);
    init_v_kernel<<<16, 256>>>();
    gemm_kernel<<<dim3(32, 32), 512, SMEM_DYN>>>(Cmat);

    for (int it = 0; it < 10; it++) {
        row_mv_kernel<<<NN, 256>>>();
        col_mv_part_kernel<<<dim3(2, 128), 256>>>();
        col_reduce_kernel<<<16, 256>>>();
    }

    final_kernel<<<NN, 256>>>(coupling, Cmat);
    loss_kernel<<<1, 1024>>>(out);
}